// round 9
// baseline (speedup 1.0000x reference)
#include <cuda_runtime.h>
#include <cuda_fp16.h>

#define NN   50000
#define NE   1250000
#define HID  64
#define NL   3
#define NG   64
#define EPSV 1e-5f
#define CAP  80          // max in-degree bucket capacity (Poisson(25): P(>80) ~ 1e-20)
#define GR   128         // gemm rows per block tile

// -------- device scratch (no runtime allocation allowed) --------
__device__ unsigned int d_hhA[NN * 32];     // half2 node features (128B/row)
__device__ unsigned int d_hhB[NN * 32];
__device__ unsigned int d_hhM[NN * 32];     // m = h @ W (half2)
__device__ int2  d_bkt[NN * CAP];           // per-dst edge buckets: (src, w-bits)
__device__ int   d_cnt[NN];                 // per-dst degree counters
__device__ float d_psum[NG * HID];
__device__ int   d_pmax[NG * HID];          // float bits; post-ReLU values >= 0
__device__ int   d_pcnt[NG];

// -------- prep: zero counters/pools + convert emb fp32 -> half2 --------
__global__ void prep_kernel(const float* __restrict__ emb) {
    int i = blockIdx.x * blockDim.x + threadIdx.x;
    int stride = gridDim.x * blockDim.x;
    for (int k = i; k < NN * 32; k += stride) {
        float2 v = ((const float2*)emb)[k];
        __half2 h = __floats2half2_rn(v.x, v.y);
        d_hhA[k] = *(unsigned int*)&h;
    }
    for (int k = i; k < NN; k += stride) d_cnt[k] = 0;
    for (int k = i; k < NG * HID; k += stride) { d_psum[k] = 0.f; d_pmax[k] = 0; }
    if (i < NG) d_pcnt[i] = 0;
}

// -------- bucket scatter: count + place edges in one pass (8-way MLP) ------
__global__ void scatter_kernel(const int* __restrict__ src, const int* __restrict__ dst,
                               const float* __restrict__ w, int ne, int T) {
    int t = blockIdx.x * blockDim.x + threadIdx.x;
    if (t >= T) return;
    int   dd[8], ss[8];
    float ww[8];
#pragma unroll
    for (int i = 0; i < 8; i++) {
        int e = t + i * T;
        bool ok = (e < ne);
        dd[i] = ok ? dst[e] : -1;
        ss[i] = ok ? src[e] : 0;
        ww[i] = ok ? w[e]   : 0.f;
    }
#pragma unroll
    for (int i = 0; i < 8; i++) {
        if (dd[i] >= 0) {
            int p = atomicAdd(&d_cnt[dd[i]], 1);
            if (p < CAP) d_bkt[dd[i] * CAP + p] = make_int2(ss[i], __float_as_int(ww[i]));
        }
    }
}

__device__ __forceinline__ float2 h2f(unsigned int bits) {
    __half2 h = *(__half2*)&bits;
    return __half22float2(h);
}

// -------- dense GEMM: m(fp16) = h(fp16) @ W(fp32) -------------------------
__global__ void __launch_bounds__(256)
gemm_kernel(const unsigned int* __restrict__ hin, const float* __restrict__ W,
            unsigned int* __restrict__ mout, int n) {
    __shared__ float Ws[HID * HID];                 // 16 KB
    __shared__ __half hs[GR][HID + 2];              // pad -> conflict-free
    int t = threadIdx.x;
    for (int i = t; i < HID * HID; i += 256) Ws[i] = W[i];
    int row0 = blockIdx.x * GR;
    for (int i = t; i < GR * 32; i += 256) {
        int r = i >> 5, c = i & 31;
        unsigned int bits = 0;
        int gr = row0 + r;
        if (gr < n) bits = hin[(size_t)gr * 32 + c];
        *(unsigned int*)&hs[r][c * 2] = bits;
    }
    __syncthreads();

    int tx = t & 7;        // cols tx*8 .. tx*8+7
    int ty = t >> 3;       // rows ty, ty+32, ty+64, ty+96
    float acc[4][8];
#pragma unroll
    for (int r = 0; r < 4; r++)
#pragma unroll
        for (int j = 0; j < 8; j++) acc[r][j] = 0.f;

#pragma unroll 8
    for (int k = 0; k < HID; k++) {
        float4 wa = *(const float4*)&Ws[k * HID + tx * 8];
        float4 wb = *(const float4*)&Ws[k * HID + tx * 8 + 4];
        float hv[4];
        hv[0] = __half2float(hs[ty][k]);
        hv[1] = __half2float(hs[ty + 32][k]);
        hv[2] = __half2float(hs[ty + 64][k]);
        hv[3] = __half2float(hs[ty + 96][k]);
#pragma unroll
        for (int r = 0; r < 4; r++) {
            acc[r][0] += hv[r] * wa.x;
            acc[r][1] += hv[r] * wa.y;
            acc[r][2] += hv[r] * wa.z;
            acc[r][3] += hv[r] * wa.w;
            acc[r][4] += hv[r] * wb.x;
            acc[r][5] += hv[r] * wb.y;
            acc[r][6] += hv[r] * wb.z;
            acc[r][7] += hv[r] * wb.w;
        }
    }

#pragma unroll
    for (int r = 0; r < 4; r++) {
        int gr = row0 + ty + r * 32;
        if (gr < n) {
#pragma unroll
            for (int j = 0; j < 4; j++) {
                __half2 hv = __floats2half2_rn(acc[r][2 * j], acc[r][2 * j + 1]);
                mout[(size_t)gr * 32 + tx * 4 + j] = *(unsigned int*)&hv;
            }
        }
    }
}

// -------- aggregate(m) -> +b -> LN -> ReLU [-> pool] ----------------------
// TWO nodes per warp (16 lanes each, uint2 = 4 halves/lane). Edge descriptors
// staged via smem; one LDG.64 gathers one edge-row for BOTH nodes.
__global__ void __launch_bounds__(256)
agg_kernel(const unsigned int* __restrict__ m,
           const float* __restrict__ cB,
           const float* __restrict__ lg,
           const float* __restrict__ lb,
           unsigned int* __restrict__ hout,
           const int* __restrict__ batch,
           int do_pool, int n) {
    __shared__ float sB[HID], sG[HID], sLb[HID];
    __shared__ int2  se[8][2][16];                  // per-warp edge stage
    int t = threadIdx.x;
    if (t < HID) { sB[t] = cB[t]; sG[t] = lg[t]; sLb[t] = lb[t]; }
    __syncthreads();

    int warp = t >> 5, lane = t & 31;
    int h = lane >> 4, sub = lane & 15;
    int nwarp = blockDim.x >> 5;
    int npairs = (n + 1) >> 1;
    const uint2* m2 = (const uint2*)m;

    for (int pair = blockIdx.x * nwarp + warp; pair < npairs; pair += gridDim.x * nwarp) {
        int node = 2 * pair + h;
        bool valid = (node < n);
        int cnt = valid ? min(d_cnt[node], CAP) : 0;
        int maxc = max(cnt, __shfl_xor_sync(0xffffffffu, cnt, 16));
        const int2* eb = d_bkt + (size_t)node * CAP;

        float4 acc = make_float4(0.f, 0.f, 0.f, 0.f);
        for (int base = 0; base < maxc; base += 16) {
            int idx = base + sub;
            int2 pe = (idx < cnt) ? eb[idx] : make_int2(0, 0);  // w=0 pad: harmless row-0 gather
            se[warp][h][sub] = pe;
            __syncwarp();
#pragma unroll
            for (int j = 0; j < 16; j++) {
                int2 p = se[warp][h][j];
                uint2 g = __ldg(m2 + (size_t)p.x * 16 + sub);
                float w = __int_as_float(p.y);
                float2 v0 = h2f(g.x);
                float2 v1 = h2f(g.y);
                acc.x += v0.x * w; acc.y += v0.y * w;
                acc.z += v1.x * w; acc.w += v1.y * w;
            }
            __syncwarp();
        }

        // bias
        float4 b4 = *(const float4*)&sB[sub * 4];
        acc.x += b4.x; acc.y += b4.y; acc.z += b4.z; acc.w += b4.w;

        // LayerNorm over 64 (16-lane half-warp reduction) + ReLU
        float sum = (acc.x + acc.y) + (acc.z + acc.w);
#pragma unroll
        for (int o = 8; o > 0; o >>= 1) sum += __shfl_xor_sync(0xffffffffu, sum, o);
        float mu = sum * (1.f / 64.f);
        float dx0 = acc.x - mu, dx1 = acc.y - mu, dx2 = acc.z - mu, dx3 = acc.w - mu;
        float v2 = (dx0 * dx0 + dx1 * dx1) + (dx2 * dx2 + dx3 * dx3);
#pragma unroll
        for (int o = 8; o > 0; o >>= 1) v2 += __shfl_xor_sync(0xffffffffu, v2, o);
        float inv = rsqrtf(v2 * (1.f / 64.f) + EPSV);
        float4 g4 = *(const float4*)&sG[sub * 4];
        float4 l4 = *(const float4*)&sLb[sub * 4];
        float r0 = fmaxf(dx0 * inv * g4.x + l4.x, 0.f);
        float r1 = fmaxf(dx1 * inv * g4.y + l4.y, 0.f);
        float r2 = fmaxf(dx2 * inv * g4.z + l4.z, 0.f);
        float r3 = fmaxf(dx3 * inv * g4.w + l4.w, 0.f);

        if (valid) {
            if (do_pool) {
                int b = batch[node];
                int c0 = b * HID + sub * 4;
                atomicAdd(&d_psum[c0 + 0], r0);
                atomicAdd(&d_psum[c0 + 1], r1);
                atomicAdd(&d_psum[c0 + 2], r2);
                atomicAdd(&d_psum[c0 + 3], r3);
                atomicMax(&d_pmax[c0 + 0], __float_as_int(r0));
                atomicMax(&d_pmax[c0 + 1], __float_as_int(r1));
                atomicMax(&d_pmax[c0 + 2], __float_as_int(r2));
                atomicMax(&d_pmax[c0 + 3], __float_as_int(r3));
                if (sub == 0) atomicAdd(&d_pcnt[b], 1);
            } else {
                __half2 o0 = __floats2half2_rn(r0, r1);
                __half2 o1 = __floats2half2_rn(r2, r3);
                uint2 ov = make_uint2(*(unsigned int*)&o0, *(unsigned int*)&o1);
                ((uint2*)hout)[(size_t)node * 16 + sub] = ov;
            }
        }
    }
}

// -------- final MLP --------
__global__ void mlp_kernel(const float* __restrict__ W1, const float* __restrict__ b1,
                           const float* __restrict__ W2, const float* __restrict__ b2,
                           float* __restrict__ out) {
    __shared__ float g[2 * HID];
    __shared__ float hr[HID];
    int gi = blockIdx.x, j = threadIdx.x;
    int cnt = d_pcnt[gi];
    float c = fmaxf((float)cnt, 1.f);
    g[j] = d_psum[gi * HID + j] / c;
    g[HID + j] = (cnt > 0) ? __int_as_float(d_pmax[gi * HID + j]) : 0.f;
    __syncthreads();
    float acc = b1[j];
#pragma unroll
    for (int k = 0; k < 2 * HID; k++) acc += g[k] * W1[k * HID + j];
    acc = fmaxf(acc, 0.f);
    hr[j] = acc * W2[j];
    __syncthreads();
    if (j < 32) {
        float s = hr[j] + hr[j + 32];
#pragma unroll
        for (int o = 16; o > 0; o >>= 1) s += __shfl_xor_sync(0xffffffffu, s, o);
        if (j == 0) out[gi] = s + b2[0];
    }
}

extern "C" void kernel_launch(void* const* d_in, const int* in_sizes, int n_in,
                              void* d_out, int out_size) {
    const int*   edge_index = (const int*)d_in[1];
    const float* edge_w     = (const float*)d_in[2];
    const int*   batch      = (const int*)d_in[3];
    const float* emb        = (const float*)d_in[4];
    const float* convW      = (const float*)d_in[5];
    const float* convB      = (const float*)d_in[6];
    const float* lnG        = (const float*)d_in[7];
    const float* lnB        = (const float*)d_in[8];
    const float* W1         = (const float*)d_in[9];
    const float* b1         = (const float*)d_in[10];
    const float* W2         = (const float*)d_in[11];
    const float* b2         = (const float*)d_in[12];
    float* out = (float*)d_out;

    int ne = in_sizes[2];
    int n  = in_sizes[3];
    const int* src = edge_index;
    const int* dst = edge_index + ne;

    unsigned int *hA, *hB, *hM;
    cudaGetSymbolAddress((void**)&hA, d_hhA);
    cudaGetSymbolAddress((void**)&hB, d_hhB);
    cudaGetSymbolAddress((void**)&hM, d_hhM);

    prep_kernel<<<1184, 256>>>(emb);
    int T = (ne + 7) / 8;
    scatter_kernel<<<(T + 255) / 256, 256>>>(src, dst, edge_w, ne, T);

    const int THREADS = 256;
    const int WARPS_PER_BLK = THREADS / 32;
    int npairs = (n + 1) / 2;
    int agg_blocks = (npairs + 4 * WARPS_PER_BLK - 1) / (4 * WARPS_PER_BLK);  // ~4 pairs/warp
    int gemm_blocks = (n + GR - 1) / GR;

    // L0: hA -> m -> hB ; L1: hB -> m -> hA ; L2: hA -> m -> pool
    gemm_kernel<<<gemm_blocks, THREADS>>>(hA, convW + 0 * HID * HID, hM, n);
    agg_kernel<<<agg_blocks, THREADS>>>(hM, convB + 0 * HID, lnG + 0 * HID,
                                        lnB + 0 * HID, hB, batch, 0, n);
    gemm_kernel<<<gemm_blocks, THREADS>>>(hB, convW + 1 * HID * HID, hM, n);
    agg_kernel<<<agg_blocks, THREADS>>>(hM, convB + 1 * HID, lnG + 1 * HID,
                                        lnB + 1 * HID, hA, batch, 0, n);
    gemm_kernel<<<gemm_blocks, THREADS>>>(hA, convW + 2 * HID * HID, hM, n);
    agg_kernel<<<agg_blocks, THREADS>>>(hM, convB + 2 * HID, lnG + 2 * HID,
                                        lnB + 2 * HID, (unsigned int*)nullptr, batch, 1, n);

    mlp_kernel<<<NG, HID>>>(W1, b1, W2, b2, out);
}